// round 6
// baseline (speedup 1.0000x reference)
#include <cuda_runtime.h>
#include <math.h>
#include <stdint.h>

#define BB 4
#define TT 2048
#define CC 1024
#define HH 64
#define NROWS (BB * TT)   // 8192

__device__ float g_q[NROWS * HH];
__device__ float g_k[NROWS * HH];
__device__ float g_v[NROWS * HH];
__device__ unsigned int g_ctr;

typedef unsigned long long ull;

// ---------------- f32x2 helpers ----------------
__device__ __forceinline__ void ffma2(ull& d, ull a, ull b) {
    asm("fma.rn.f32x2 %0, %1, %2, %0;" : "+l"(d) : "l"(a), "l"(b));
}
__device__ __forceinline__ void fmul2(ull& d, ull a) {
    asm("mul.rn.f32x2 %0, %0, %1;" : "+l"(d) : "l"(a));
}
__device__ __forceinline__ ull pack2(float lo, float hi) {
    ull r; asm("mov.b64 %0, {%1, %2};" : "=l"(r) : "f"(lo), "f"(hi)); return r;
}
__device__ __forceinline__ void unpack2(ull v, float& a, float& b) {
    asm("mov.b64 {%0, %1}, %2;" : "=f"(a), "=f"(b) : "l"(v));
}
__device__ __forceinline__ void lds_2x64(ull& a, ull& b, const void* p) {
    uint32_t sa = (uint32_t)__cvta_generic_to_shared(p);
    asm volatile("ld.shared.v2.u64 {%0, %1}, [%2];" : "=l"(a), "=l"(b) : "r"(sa));
}
__device__ __forceinline__ ull lds_u64(const void* p) {
    uint32_t sa = (uint32_t)__cvta_generic_to_shared(p);
    ull r;
    asm volatile("ld.shared.u64 %0, [%1];" : "=l"(r) : "r"(sa));
    return r;
}
__device__ __forceinline__ void cp_async16(void* smem_dst, const void* gptr) {
    uint32_t sa = (uint32_t)__cvta_generic_to_shared(smem_dst);
    asm volatile("cp.async.cg.shared.global [%0], [%1], 16;" :: "r"(sa), "l"(gptr));
}
#define CP_COMMIT() asm volatile("cp.async.commit_group;")
#define CP_WAIT(n)  asm volatile("cp.async.wait_group %0;" :: "n"(n))

__global__ void reset_ctr_kernel() { g_ctr = 0u; }

// ---------------------------------------------------------------------------
// Kernel 1: QKV projection (unchanged from best: ~90us).
// BM=64, BN=64, BK=32, 128 threads, thread tile 8m x 4n, m-pair f32x2.
// ---------------------------------------------------------------------------
__global__ __launch_bounds__(128) void proj_kernel(
    const float* __restrict__ x,
    const float* __restrict__ Wq,
    const float* __restrict__ Wk,
    const float* __restrict__ Wv)
{
    const float* W = (blockIdx.y == 0) ? Wq : (blockIdx.y == 1) ? Wk : Wv;
    float* out     = (blockIdx.y == 0) ? g_q : (blockIdx.y == 1) ? g_k : g_v;

    __shared__ float As[2][32][68];
    __shared__ float Bs[2][32][64];

    const int tid  = threadIdx.x;
    const int tm   = tid >> 4;
    const int tn   = tid & 15;
    const int row0 = blockIdx.x * 64;

    int arow[4], akc[4];
#pragma unroll
    for (int s = 0; s < 4; s++) {
        const int ch = tid + s * 128;
        arow[s] = ch >> 3;
        akc[s]  = ch & 7;
    }
    ull acc[4][4] = {};
    float4 ar[4];

#pragma unroll
    for (int s = 0; s < 4; s++)
        ar[s] = *(const float4*)&x[(row0 + arow[s]) * CC + akc[s] * 4];
#pragma unroll
    for (int s = 0; s < 4; s++) {
        const int ch = tid + s * 128;
        const int k = ch >> 4, nc = ch & 15;
        cp_async16(&Bs[0][k][nc * 4], &W[k * HH + nc * 4]);
    }
    CP_COMMIT();
#pragma unroll
    for (int s = 0; s < 4; s++) {
        As[0][akc[s] * 4 + 0][arow[s]] = ar[s].x;
        As[0][akc[s] * 4 + 1][arow[s]] = ar[s].y;
        As[0][akc[s] * 4 + 2][arow[s]] = ar[s].z;
        As[0][akc[s] * 4 + 3][arow[s]] = ar[s].w;
    }
#pragma unroll
    for (int s = 0; s < 4; s++)
        ar[s] = *(const float4*)&x[(row0 + arow[s]) * CC + 32 + akc[s] * 4];
    CP_WAIT(0);
    __syncthreads();

    for (int t = 0; t < 32; t++) {
        const int buf = t & 1;
        if (t < 31) {
            const int k0n = (t + 1) * 32;
#pragma unroll
            for (int s = 0; s < 4; s++) {
                const int ch = tid + s * 128;
                const int k = ch >> 4, nc = ch & 15;
                cp_async16(&Bs[buf ^ 1][k][nc * 4], &W[(k0n + k) * HH + nc * 4]);
            }
            CP_COMMIT();
#pragma unroll
            for (int s = 0; s < 4; s++) {
                As[buf ^ 1][akc[s] * 4 + 0][arow[s]] = ar[s].x;
                As[buf ^ 1][akc[s] * 4 + 1][arow[s]] = ar[s].y;
                As[buf ^ 1][akc[s] * 4 + 2][arow[s]] = ar[s].z;
                As[buf ^ 1][akc[s] * 4 + 3][arow[s]] = ar[s].w;
            }
        }

#pragma unroll 16
        for (int k = 0; k < 32; k++) {
            ull a01, a23, a45, a67;
            lds_2x64(a01, a23, &As[buf][k][tm * 8]);
            lds_2x64(a45, a67, &As[buf][k][tm * 8 + 4]);
            float4 b4 = *(const float4*)&Bs[buf][k][tn * 4];
            const ull b0 = pack2(b4.x, b4.x);
            const ull b1 = pack2(b4.y, b4.y);
            const ull b2 = pack2(b4.z, b4.z);
            const ull b3 = pack2(b4.w, b4.w);
            ffma2(acc[0][0], a01, b0); ffma2(acc[0][1], a01, b1);
            ffma2(acc[0][2], a01, b2); ffma2(acc[0][3], a01, b3);
            ffma2(acc[1][0], a23, b0); ffma2(acc[1][1], a23, b1);
            ffma2(acc[1][2], a23, b2); ffma2(acc[1][3], a23, b3);
            ffma2(acc[2][0], a45, b0); ffma2(acc[2][1], a45, b1);
            ffma2(acc[2][2], a45, b2); ffma2(acc[2][3], a45, b3);
            ffma2(acc[3][0], a67, b0); ffma2(acc[3][1], a67, b1);
            ffma2(acc[3][2], a67, b2); ffma2(acc[3][3], a67, b3);
        }

        if (t < 31) {
            if (t < 30) {
                const int k0nn = (t + 2) * 32;
#pragma unroll
                for (int s = 0; s < 4; s++)
                    ar[s] = *(const float4*)&x[(row0 + arow[s]) * CC + k0nn + akc[s] * 4];
            }
            CP_WAIT(0);
            __syncthreads();
        }
    }

#pragma unroll
    for (int mp = 0; mp < 4; mp++) {
        float lo0, hi0, lo1, hi1, lo2, hi2, lo3, hi3;
        unpack2(acc[mp][0], lo0, hi0);
        unpack2(acc[mp][1], lo1, hi1);
        unpack2(acc[mp][2], lo2, hi2);
        unpack2(acc[mp][3], lo3, hi3);
        float* r0 = &out[(row0 + tm * 8 + 2 * mp) * HH + tn * 4];
        float* r1 = &out[(row0 + tm * 8 + 2 * mp + 1) * HH + tn * 4];
        *(float4*)r0 = make_float4(lo0, lo1, lo2, lo3);
        *(float4*)r1 = make_float4(hi0, hi1, hi2, hi3);
    }
}

// ---------------------------------------------------------------------------
// Kernel 2: persistent work-stealing causal attention.
// 296 blocks x 128 threads (4 warps, 8 rows/warp). Work item = (qt, b):
// one 32-row q-tile, heavy tiles first. 64-key cp.async double-buffered.
// Lane l: score cols / out dims {l, l+32}. PV: j-pair f32x2.
// smem 80KB -> 2 blocks/SM.
// ---------------------------------------------------------------------------
#define SMA_K(buf)  (sm + (buf) * 4096)            // [64][64] swizzled
#define SMA_V(buf)  (sm + 8192 + (buf) * 4096)     // [64][64] linear
#define SMA_Q       (sm + 16384)                   // [32][64]
#define SMA_PW      (sm + 18432)                   // [4][8][64]
#define ATTN_SMEM_BYTES ((18432 + 2048) * 4)       // 81920 = 80KB
#define N_ITEMS 256

__global__ __launch_bounds__(128) void attn_kernel(float* __restrict__ out)
{
    extern __shared__ float sm[];
    __shared__ unsigned int s_item;

    const int tid = threadIdx.x;
    const int w   = tid >> 5;
    const int l   = tid & 31;

    float* pw = SMA_PW + (w << 9);    // [8][64]

    while (true) {
        __syncthreads();              // smem from previous item fully consumed
        if (tid == 0) s_item = atomicAdd(&g_ctr, 1u);
        __syncthreads();
        const unsigned int item = s_item;
        if (item >= N_ITEMS) break;

        const int qt = 63 - (int)(item >> 2);   // heavy q-tiles first
        const int b  = (int)(item & 3u);
        const int qs = qt * 32;

        const float* qb = g_q + b * TT * HH;
        const float* kb = g_k + b * TT * HH;
        const float* vb = g_v + b * TT * HH;
        float*       ob = out + b * TT * HH;

        const int nkb = (qs + 32 + 63) >> 6;

        // ---- prologue: Q + K0/V0 via cp.async ----
#pragma unroll
        for (int s = 0; s < 4; s++) {
            const int ch = tid + s * 128;         // 0..511
            cp_async16(SMA_Q + ch * 4, &qb[qs * 64 + ch * 4]);
        }
#pragma unroll
        for (int s = 0; s < 8; s++) {
            const int ch = tid + s * 128;         // 0..1023
            const int row = ch >> 4, c4 = ch & 15;
            cp_async16(SMA_K(0) + row * 64 + ((c4 ^ (row & 7)) << 2),
                       &kb[row * 64 + c4 * 4]);
            cp_async16(SMA_V(0) + row * 64 + c4 * 4, &vb[row * 64 + c4 * 4]);
        }
        CP_COMMIT();

        float m[8], lsum[8];
        ull accL[8], accH[8];
#pragma unroll
        for (int i = 0; i < 8; i++) {
            m[i] = -INFINITY; lsum[i] = 0.f; accL[i] = 0ull; accH[i] = 0ull;
        }

        for (int t = 0; t < nkb; t++) {
            const int buf = t & 1;
            CP_WAIT(0);
            __syncthreads();          // tile t (and Q) ready; prev buf free

            if (t + 1 < nkb) {
                const float* kn = &kb[(t + 1) * 64 * 64];
                const float* vn = &vb[(t + 1) * 64 * 64];
#pragma unroll
                for (int s = 0; s < 8; s++) {
                    const int ch = tid + s * 128;
                    const int row = ch >> 4, c4 = ch & 15;
                    cp_async16(SMA_K(buf ^ 1) + row * 64 + ((c4 ^ (row & 7)) << 2),
                               kn + row * 64 + c4 * 4);
                    cp_async16(SMA_V(buf ^ 1) + row * 64 + c4 * 4,
                               vn + row * 64 + c4 * 4);
                }
                CP_COMMIT();
            }

            const float* Ks = SMA_K(buf);
            const float* Vb = SMA_V(buf);

            // ---- scores: 8 rows/warp, k-packed f32x2 ----
            ull s2[8][2] = {};
#pragma unroll
            for (int c4 = 0; c4 < 16; c4++) {
                ull kl0, kl1, kh0, kh1;
                lds_2x64(kl0, kl1, &Ks[l * 64 + ((c4 ^ (l & 7)) << 2)]);
                lds_2x64(kh0, kh1, &Ks[(l + 32) * 64 + ((c4 ^ ((l + 32) & 7)) << 2)]);
#pragma unroll
                for (int i = 0; i < 8; i++) {
                    ull q0, q1;
                    lds_2x64(q0, q1, &SMA_Q[((w << 3) + i) * 64 + c4 * 4]);
                    ffma2(s2[i][0], q0, kl0); ffma2(s2[i][0], q1, kl1);
                    ffma2(s2[i][1], q0, kh0); ffma2(s2[i][1], q1, kh1);
                }
            }

            // ---- online softmax, exact reference mask ----
            const int col0 = t * 64 + l;
            const int col1 = col0 + 32;
#pragma unroll
            for (int i = 0; i < 8; i++) {
                const int rowg = qs + (w << 3) + i;
                float lo, hi, sc0, sc1;
                unpack2(s2[i][0], lo, hi);  sc0 = (lo + hi) * 0.125f;
                unpack2(s2[i][1], lo, hi);  sc1 = (lo + hi) * 0.125f;
                if (col0 > rowg || sc0 == 0.0f) sc0 = -INFINITY;
                if (col1 > rowg || sc1 == 0.0f) sc1 = -INFINITY;

                float rmax = fmaxf(sc0, sc1);
#pragma unroll
                for (int off = 16; off > 0; off >>= 1)
                    rmax = fmaxf(rmax, __shfl_xor_sync(0xffffffffu, rmax, off));

                const float mnew = fmaxf(m[i], rmax);
                const float f    = __expf(m[i] - mnew);
                const float p0   = __expf(sc0 - mnew);
                const float p1   = __expf(sc1 - mnew);

                float psum = p0 + p1;
#pragma unroll
                for (int off = 16; off > 0; off >>= 1)
                    psum += __shfl_xor_sync(0xffffffffu, psum, off);

                lsum[i] = lsum[i] * f + psum;
                m[i] = mnew;
                const ull f2 = pack2(f, f);
                fmul2(accL[i], f2);
                fmul2(accH[i], f2);
                pw[(i << 6) + l]      = p0;
                pw[(i << 6) + l + 32] = p1;
            }
            __syncwarp();

            // ---- P @ V : j-pairs packed; p-pair = free 8B broadcast ----
#pragma unroll 4
            for (int jq = 0; jq < 32; jq++) {
                const int j = jq * 2;
                const ull vvL = pack2(Vb[j * 64 + l],      Vb[(j + 1) * 64 + l]);
                const ull vvH = pack2(Vb[j * 64 + l + 32], Vb[(j + 1) * 64 + l + 32]);
#pragma unroll
                for (int i = 0; i < 8; i++) {
                    const ull p2 = lds_u64(&pw[(i << 6) + j]);
                    ffma2(accL[i], p2, vvL);
                    ffma2(accH[i], p2, vvH);
                }
            }
            __syncthreads();          // all warps done with buf before refill
        }

        // ---- epilogue: horizontal add of j-pair halves ----
#pragma unroll
        for (int i = 0; i < 8; i++) {
            const int rowg = qs + (w << 3) + i;
            const float inv = 1.0f / lsum[i];
            float lo, hi;
            unpack2(accL[i], lo, hi);
            ob[rowg * HH + l] = (lo + hi) * inv;
            unpack2(accH[i], lo, hi);
            ob[rowg * HH + l + 32] = (lo + hi) * inv;
        }
    }
}

// ---------------------------------------------------------------------------
extern "C" void kernel_launch(void* const* d_in, const int* in_sizes, int n_in,
                              void* d_out, int out_size)
{
    const float* x  = (const float*)d_in[0];
    const float* Wq = (const float*)d_in[1];
    const float* Wk = (const float*)d_in[2];
    const float* Wv = (const float*)d_in[3];
    float* out = (float*)d_out;

    static int smem_set = 0;
    if (!smem_set) {
        cudaFuncSetAttribute(attn_kernel,
                             cudaFuncAttributeMaxDynamicSharedMemorySize,
                             ATTN_SMEM_BYTES);
        smem_set = 1;
    }

    reset_ctr_kernel<<<1, 1>>>();
    proj_kernel<<<dim3(NROWS / 64, 3), 128>>>(x, Wq, Wk, Wv);
    attn_kernel<<<296, 128, ATTN_SMEM_BYTES>>>(out);
}

// round 7
// speedup vs baseline: 1.3382x; 1.3382x over previous
#include <cuda_runtime.h>
#include <math.h>
#include <stdint.h>

#define BB 4
#define TT 2048
#define CC 1024
#define HH 64
#define NROWS (BB * TT)   // 8192

__device__ float g_q[NROWS * HH];
__device__ float g_k[NROWS * HH];
__device__ float g_v[NROWS * HH];

typedef unsigned long long ull;

// ---------------- f32x2 helpers ----------------
__device__ __forceinline__ void ffma2(ull& d, ull a, ull b) {
    asm("fma.rn.f32x2 %0, %1, %2, %0;" : "+l"(d) : "l"(a), "l"(b));
}
__device__ __forceinline__ void fmul2(ull& d, ull a) {
    asm("mul.rn.f32x2 %0, %0, %1;" : "+l"(d) : "l"(a));
}
__device__ __forceinline__ ull pack2(float lo, float hi) {
    ull r; asm("mov.b64 %0, {%1, %2};" : "=l"(r) : "f"(lo), "f"(hi)); return r;
}
__device__ __forceinline__ void unpack2(ull v, float& a, float& b) {
    asm("mov.b64 {%0, %1}, %2;" : "=f"(a), "=f"(b) : "l"(v));
}
__device__ __forceinline__ void lds_2x64(ull& a, ull& b, const void* p) {
    uint32_t sa = (uint32_t)__cvta_generic_to_shared(p);
    asm volatile("ld.shared.v2.u64 {%0, %1}, [%2];" : "=l"(a), "=l"(b) : "r"(sa));
}
__device__ __forceinline__ void cp_async16(void* smem_dst, const void* gptr) {
    uint32_t sa = (uint32_t)__cvta_generic_to_shared(smem_dst);
    asm volatile("cp.async.cg.shared.global [%0], [%1], 16;" :: "r"(sa), "l"(gptr));
}
#define CP_COMMIT() asm volatile("cp.async.commit_group;")
#define CP_WAIT(n)  asm volatile("cp.async.wait_group %0;" :: "n"(n))

// ---------------------------------------------------------------------------
// Kernel 1: QKV projection (best so far ~90us, unchanged).
// BM=64, BN=64, BK=32, 128 threads, thread tile 8m x 4n, m-pair f32x2.
// ---------------------------------------------------------------------------
__global__ __launch_bounds__(128) void proj_kernel(
    const float* __restrict__ x,
    const float* __restrict__ Wq,
    const float* __restrict__ Wk,
    const float* __restrict__ Wv)
{
    const float* W = (blockIdx.y == 0) ? Wq : (blockIdx.y == 1) ? Wk : Wv;
    float* out     = (blockIdx.y == 0) ? g_q : (blockIdx.y == 1) ? g_k : g_v;

    __shared__ float As[2][32][68];
    __shared__ float Bs[2][32][64];

    const int tid  = threadIdx.x;
    const int tm   = tid >> 4;
    const int tn   = tid & 15;
    const int row0 = blockIdx.x * 64;

    int arow[4], akc[4];
#pragma unroll
    for (int s = 0; s < 4; s++) {
        const int ch = tid + s * 128;
        arow[s] = ch >> 3;
        akc[s]  = ch & 7;
    }
    ull acc[4][4] = {};
    float4 ar[4];

#pragma unroll
    for (int s = 0; s < 4; s++)
        ar[s] = *(const float4*)&x[(row0 + arow[s]) * CC + akc[s] * 4];
#pragma unroll
    for (int s = 0; s < 4; s++) {
        const int ch = tid + s * 128;
        const int k = ch >> 4, nc = ch & 15;
        cp_async16(&Bs[0][k][nc * 4], &W[k * HH + nc * 4]);
    }
    CP_COMMIT();
#pragma unroll
    for (int s = 0; s < 4; s++) {
        As[0][akc[s] * 4 + 0][arow[s]] = ar[s].x;
        As[0][akc[s] * 4 + 1][arow[s]] = ar[s].y;
        As[0][akc[s] * 4 + 2][arow[s]] = ar[s].z;
        As[0][akc[s] * 4 + 3][arow[s]] = ar[s].w;
    }
#pragma unroll
    for (int s = 0; s < 4; s++)
        ar[s] = *(const float4*)&x[(row0 + arow[s]) * CC + 32 + akc[s] * 4];
    CP_WAIT(0);
    __syncthreads();

    for (int t = 0; t < 32; t++) {
        const int buf = t & 1;
        if (t < 31) {
            const int k0n = (t + 1) * 32;
#pragma unroll
            for (int s = 0; s < 4; s++) {
                const int ch = tid + s * 128;
                const int k = ch >> 4, nc = ch & 15;
                cp_async16(&Bs[buf ^ 1][k][nc * 4], &W[(k0n + k) * HH + nc * 4]);
            }
            CP_COMMIT();
#pragma unroll
            for (int s = 0; s < 4; s++) {
                As[buf ^ 1][akc[s] * 4 + 0][arow[s]] = ar[s].x;
                As[buf ^ 1][akc[s] * 4 + 1][arow[s]] = ar[s].y;
                As[buf ^ 1][akc[s] * 4 + 2][arow[s]] = ar[s].z;
                As[buf ^ 1][akc[s] * 4 + 3][arow[s]] = ar[s].w;
            }
        }

#pragma unroll 16
        for (int k = 0; k < 32; k++) {
            ull a01, a23, a45, a67;
            lds_2x64(a01, a23, &As[buf][k][tm * 8]);
            lds_2x64(a45, a67, &As[buf][k][tm * 8 + 4]);
            float4 b4 = *(const float4*)&Bs[buf][k][tn * 4];
            const ull b0 = pack2(b4.x, b4.x);
            const ull b1 = pack2(b4.y, b4.y);
            const ull b2 = pack2(b4.z, b4.z);
            const ull b3 = pack2(b4.w, b4.w);
            ffma2(acc[0][0], a01, b0); ffma2(acc[0][1], a01, b1);
            ffma2(acc[0][2], a01, b2); ffma2(acc[0][3], a01, b3);
            ffma2(acc[1][0], a23, b0); ffma2(acc[1][1], a23, b1);
            ffma2(acc[1][2], a23, b2); ffma2(acc[1][3], a23, b3);
            ffma2(acc[2][0], a45, b0); ffma2(acc[2][1], a45, b1);
            ffma2(acc[2][2], a45, b2); ffma2(acc[2][3], a45, b3);
            ffma2(acc[3][0], a67, b0); ffma2(acc[3][1], a67, b1);
            ffma2(acc[3][2], a67, b2); ffma2(acc[3][3], a67, b3);
        }

        if (t < 31) {
            if (t < 30) {
                const int k0nn = (t + 2) * 32;
#pragma unroll
                for (int s = 0; s < 4; s++)
                    ar[s] = *(const float4*)&x[(row0 + arow[s]) * CC + k0nn + akc[s] * 4];
            }
            CP_WAIT(0);
            __syncthreads();
        }
    }

#pragma unroll
    for (int mp = 0; mp < 4; mp++) {
        float lo0, hi0, lo1, hi1, lo2, hi2, lo3, hi3;
        unpack2(acc[mp][0], lo0, hi0);
        unpack2(acc[mp][1], lo1, hi1);
        unpack2(acc[mp][2], lo2, hi2);
        unpack2(acc[mp][3], lo3, hi3);
        float* r0 = &out[(row0 + tm * 8 + 2 * mp) * HH + tn * 4];
        float* r1 = &out[(row0 + tm * 8 + 2 * mp + 1) * HH + tn * 4];
        *(float4*)r0 = make_float4(lo0, lo1, lo2, lo3);
        *(float4*)r1 = make_float4(hi0, hi1, hi2, hi3);
    }
}

// ---------------------------------------------------------------------------
// Kernel 2: causal attention. 512 independent blocks (heavy q-tiles first),
// 128 threads (4 warps, 4 rows/warp), 16-row q-tile per block, 64-key tiles
// with full cp.async double buffering. smem 72KB -> 3 blocks/SM (12 warps/SM).
// Lane l: score cols / out dims {l, l+32}. PV: row-pair f32x2 + transposed P.
// ---------------------------------------------------------------------------
#define SMA_K(buf)  (sm + (buf) * 4096)            // [64][64] swizzled
#define SMA_V(buf)  (sm + 8192 + (buf) * 4096)     // [64][64] linear
#define SMA_Q       (sm + 16384)                   // [16][64]
#define SMA_PT      (sm + 17408)                   // [4][64][4]
#define ATTN_SMEM_BYTES (18432 * 4)                // 73728 = 72KB

__global__ __launch_bounds__(128) void attn_kernel(float* __restrict__ out)
{
    extern __shared__ float sm[];

    const int bx  = blockIdx.x;
    const int qt  = 127 - (bx >> 2);   // heavy tiles dispatched first
    const int b   = bx & 3;
    const int qs  = qt * 16;
    const int tid = threadIdx.x;
    const int w   = tid >> 5;
    const int l   = tid & 31;

    const float* qb = g_q + b * TT * HH;
    const float* kb = g_k + b * TT * HH;
    const float* vb = g_v + b * TT * HH;
    float*       ob = out + b * TT * HH;

    float* pt = SMA_PT + (w << 8);     // [64][4]

    const int nkb = (qs + 16 + 63) >> 6;

    // ---- prologue: Q + K0/V0 via cp.async ----
#pragma unroll
    for (int s = 0; s < 2; s++) {
        const int ch = tid + s * 128;            // 0..255
        cp_async16(SMA_Q + ch * 4, &qb[qs * 64 + ch * 4]);
    }
#pragma unroll
    for (int s = 0; s < 8; s++) {
        const int ch = tid + s * 128;            // 0..1023
        const int row = ch >> 4, c4 = ch & 15;
        cp_async16(SMA_K(0) + row * 64 + ((c4 ^ (row & 7)) << 2),
                   &kb[row * 64 + c4 * 4]);
        cp_async16(SMA_V(0) + row * 64 + c4 * 4, &vb[row * 64 + c4 * 4]);
    }
    CP_COMMIT();

    float m[4], lsum[4];
    ull accA[2] = {0ull, 0ull};    // dim l:    {rows 0,1}, {rows 2,3}
    ull accB[2] = {0ull, 0ull};    // dim l+32
#pragma unroll
    for (int i = 0; i < 4; i++) { m[i] = -INFINITY; lsum[i] = 0.f; }

    for (int t = 0; t < nkb; t++) {
        const int buf = t & 1;
        CP_WAIT(0);
        __syncthreads();             // tile t (and Q) ready; prev buf free

        if (t + 1 < nkb) {
            const float* kn = &kb[(t + 1) * 64 * 64];
            const float* vn = &vb[(t + 1) * 64 * 64];
#pragma unroll
            for (int s = 0; s < 8; s++) {
                const int ch = tid + s * 128;
                const int row = ch >> 4, c4 = ch & 15;
                cp_async16(SMA_K(buf ^ 1) + row * 64 + ((c4 ^ (row & 7)) << 2),
                           kn + row * 64 + c4 * 4);
                cp_async16(SMA_V(buf ^ 1) + row * 64 + c4 * 4,
                           vn + row * 64 + c4 * 4);
            }
            CP_COMMIT();
        }

        const float* Ks = SMA_K(buf);
        const float* Vb = SMA_V(buf);

        // ---- scores: 4 rows/warp, k-packed f32x2 ----
        ull s2[4][2] = {};
#pragma unroll
        for (int c4 = 0; c4 < 16; c4++) {
            ull kl0, kl1, kh0, kh1;
            lds_2x64(kl0, kl1, &Ks[l * 64 + ((c4 ^ (l & 7)) << 2)]);
            lds_2x64(kh0, kh1, &Ks[(l + 32) * 64 + ((c4 ^ (l & 7)) << 2)]);
#pragma unroll
            for (int i = 0; i < 4; i++) {
                ull q0, q1;
                lds_2x64(q0, q1, &SMA_Q[((w << 2) + i) * 64 + c4 * 4]);
                ffma2(s2[i][0], q0, kl0); ffma2(s2[i][0], q1, kl1);
                ffma2(s2[i][1], q0, kh0); ffma2(s2[i][1], q1, kh1);
            }
        }

        // ---- online softmax, exact reference mask ----
        const int col0 = t * 64 + l;
        const int col1 = col0 + 32;
        float f[4];
#pragma unroll
        for (int i = 0; i < 4; i++) {
            const int rowg = qs + (w << 2) + i;
            float lo, hi, sc0, sc1;
            unpack2(s2[i][0], lo, hi);  sc0 = (lo + hi) * 0.125f;
            unpack2(s2[i][1], lo, hi);  sc1 = (lo + hi) * 0.125f;
            if (col0 > rowg || sc0 == 0.0f) sc0 = -INFINITY;
            if (col1 > rowg || sc1 == 0.0f) sc1 = -INFINITY;

            float rmax = fmaxf(sc0, sc1);
#pragma unroll
            for (int off = 16; off > 0; off >>= 1)
                rmax = fmaxf(rmax, __shfl_xor_sync(0xffffffffu, rmax, off));

            const float mnew = fmaxf(m[i], rmax);
            f[i] = __expf(m[i] - mnew);
            const float p0 = __expf(sc0 - mnew);
            const float p1 = __expf(sc1 - mnew);

            float psum = p0 + p1;
#pragma unroll
            for (int off = 16; off > 0; off >>= 1)
                psum += __shfl_xor_sync(0xffffffffu, psum, off);

            lsum[i] = lsum[i] * f[i] + psum;
            m[i] = mnew;
            pt[l * 4 + i]        = p0;
            pt[(l + 32) * 4 + i] = p1;
        }
        {
            const ull f01 = pack2(f[0], f[1]);
            const ull f23 = pack2(f[2], f[3]);
            fmul2(accA[0], f01); fmul2(accB[0], f01);
            fmul2(accA[1], f23); fmul2(accB[1], f23);
        }
        __syncwarp();

        // ---- P @ V : row-pair packed; P = 16B broadcast from transposed pt
#pragma unroll 8
        for (int j = 0; j < 64; j++) {
            ull p01, p23;
            lds_2x64(p01, p23, &pt[j * 4]);
            const float v0 = Vb[j * 64 + l];
            const float v1 = Vb[j * 64 + l + 32];
            const ull vv0 = pack2(v0, v0);
            const ull vv1 = pack2(v1, v1);
            ffma2(accA[0], p01, vv0);
            ffma2(accA[1], p23, vv0);
            ffma2(accB[0], p01, vv1);
            ffma2(accB[1], p23, vv1);
        }
        __syncthreads();             // all warps done with buf before refill
    }

    // ---- epilogue ----
    {
        const float inv0 = 1.0f / lsum[0], inv1 = 1.0f / lsum[1];
        const float inv2 = 1.0f / lsum[2], inv3 = 1.0f / lsum[3];
        float a0, a1;
        unpack2(accA[0], a0, a1);
        ob[(qs + (w << 2) + 0) * HH + l] = a0 * inv0;
        ob[(qs + (w << 2) + 1) * HH + l] = a1 * inv1;
        unpack2(accA[1], a0, a1);
        ob[(qs + (w << 2) + 2) * HH + l] = a0 * inv2;
        ob[(qs + (w << 2) + 3) * HH + l] = a1 * inv3;
        unpack2(accB[0], a0, a1);
        ob[(qs + (w << 2) + 0) * HH + l + 32] = a0 * inv0;
        ob[(qs + (w << 2) + 1) * HH + l + 32] = a1 * inv1;
        unpack2(accB[1], a0, a1);
        ob[(qs + (w << 2) + 2) * HH + l + 32] = a0 * inv2;
        ob[(qs + (w << 2) + 3) * HH + l + 32] = a1 * inv3;
    }
}

// ---------------------------------------------------------------------------
extern "C" void kernel_launch(void* const* d_in, const int* in_sizes, int n_in,
                              void* d_out, int out_size)
{
    const float* x  = (const float*)d_in[0];
    const float* Wq = (const float*)d_in[1];
    const float* Wk = (const float*)d_in[2];
    const float* Wv = (const float*)d_in[3];
    float* out = (float*)d_out;

    static int smem_set = 0;
    if (!smem_set) {
        cudaFuncSetAttribute(attn_kernel,
                             cudaFuncAttributeMaxDynamicSharedMemorySize,
                             ATTN_SMEM_BYTES);
        smem_set = 1;
    }

    proj_kernel<<<dim3(NROWS / 64, 3), 128>>>(x, Wq, Wk, Wv);
    attn_kernel<<<512, 128, ATTN_SMEM_BYTES>>>(out);
}